// round 6
// baseline (speedup 1.0000x reference)
#include <cuda_runtime.h>
#include <cuda_bf16.h>

// Analytic reduction of the 4-op "nibble machine":
//   t      = x3*(1 - x10) + x[b, tok=3, col=1]
//   rawsum = x4 + x0 * t
//   result = x5 + (k>=3 ? rawsum[b, k-3] : 0)
// all other 61 columns: identity copy.
//
// Streaming: each thread owns 8 float4s at stride 256 (block-strided); since
// 256 % 16 == 0 all eight share the same in-token position, so the patch
// branch is uniform per thread. 14/16 threads are pure LDG.128x8 ->
// STG.128x8 copies (MLP=8). 32-bit indexing throughout (offsets < 2^28).

constexpr int THREADS = 256;
constexpr int VEC = 8;                        // float4s per thread
constexpr int BLK4 = THREADS * VEC;           // 2048 float4s per block

__global__ __launch_bounds__(THREADS)
void nibble_stream8_kernel(const float* __restrict__ in, float* __restrict__ out)
{
    const unsigned i0 = blockIdx.x * BLK4 + threadIdx.x;   // float4 index

    const float4* __restrict__ in4 = reinterpret_cast<const float4*>(in);
    float4* __restrict__ out4 = reinterpret_cast<float4*>(out);

    float4 v[VEC];
#pragma unroll
    for (int j = 0; j < VEC; j++)
        v[j] = __ldcs(in4 + i0 + j * THREADS);

    const unsigned c4 = i0 & 15u;             // same for all VEC elements

    if (c4 <= 1u) {
#pragma unroll
        for (int j = 0; j < VEC; j++) {
            const unsigned i  = i0 + j * THREADS;
            const unsigned tb = (i & ~15u) * 4u;     // token base (floats)
            const unsigned rb = (i & ~127u) * 4u;    // row base   (floats)
            const float b_bc = __ldg(in + rb + 3 * 64 + 1);  // x[b,tok3,col1]

            if (c4 == 0u) {
                // v = cols {0,1,2,3}; patch col 3 (TEMP)
                const float x10 = __ldg(in + tb + 10);
                v[j].w = fmaf(v[j].w, 1.0f - x10, b_bc);
            } else {
                // v = cols {4,5,6,7}; patch col 4 (RAW_SUM), col 5 (RESULT)
                const float x0  = __ldg(in + tb + 0);
                const float x3  = __ldg(in + tb + 3);
                const float x10 = __ldg(in + tb + 10);
                const float t   = fmaf(x3, 1.0f - x10, b_bc);
                v[j].x = fmaf(x0, t, v[j].x);                 // rawsum

                const unsigned k = (i >> 4) & 7u;             // token index
                if (k >= 3u) {
                    const float* p = in + tb - 3 * 64;        // token k-3
                    const float tp = fmaf(__ldg(p + 3), 1.0f - __ldg(p + 10), b_bc);
                    v[j].y += fmaf(__ldg(p + 0), tp, __ldg(p + 4)); // + rawsum[k-3]
                }
            }
        }
    }

#pragma unroll
    for (int j = 0; j < VEC; j++)
        __stcs(out4 + i0 + j * THREADS, v[j]);
}

extern "C" void kernel_launch(void* const* d_in, const int* in_sizes, int n_in,
                              void* d_out, int out_size)
{
    const float* x = (const float*)d_in[0];
    float* out = (float*)d_out;

    int total = in_sizes[0];                  // BATCH * 8 * 64 floats
    if (total <= 0) total = out_size;
    const int total4 = total / 4;             // float4 count (16,777,216)
    const int blocks = total4 / BLK4;         // 8192
    nibble_stream8_kernel<<<blocks, THREADS>>>(x, out);
}

// round 7
// speedup vs baseline: 1.1376x; 1.1376x over previous
#include <cuda_runtime.h>
#include <cuda_bf16.h>

// Analytic reduction of the 4-op "nibble machine":
//   t      = x3*(1 - x10) + x[b, tok=3, col=1]
//   rawsum = x4 + x0 * t
//   result = x5 + (k>=3 ? rawsum[b, k-3] : 0)
// all other 61 columns: identity copy.
//
// VEC=4 block-strided float4 streaming (best occupancy/MLP balance: R5=82.7us
// at occ 84%; VEC=8 regressed to 98us from register pressure). This round
// keeps VEC=4 and adds 32-bit indexing + ldcs/stcs streaming hints.

constexpr int THREADS = 256;
constexpr int VEC = 4;                        // float4s per thread
constexpr int BLK4 = THREADS * VEC;           // 1024 float4s per block

__global__ __launch_bounds__(THREADS)
void nibble_stream4b_kernel(const float* __restrict__ in, float* __restrict__ out)
{
    const unsigned i0 = blockIdx.x * BLK4 + threadIdx.x;   // float4 index

    const float4* __restrict__ in4 = reinterpret_cast<const float4*>(in);
    float4* __restrict__ out4 = reinterpret_cast<float4*>(out);

    float4 v[VEC];
#pragma unroll
    for (int j = 0; j < VEC; j++)
        v[j] = __ldcs(in4 + i0 + j * THREADS);

    const unsigned c4 = i0 & 15u;             // same for all VEC elements

    if (c4 <= 1u) {
#pragma unroll
        for (int j = 0; j < VEC; j++) {
            const unsigned i  = i0 + j * THREADS;
            const unsigned tb = (i & ~15u) * 4u;     // token base (floats)
            const unsigned rb = (i & ~127u) * 4u;    // row base   (floats)
            const float b_bc = __ldg(in + rb + 3 * 64 + 1);  // x[b,tok3,col1]

            if (c4 == 0u) {
                // v = cols {0,1,2,3}; patch col 3 (TEMP)
                const float x10 = __ldg(in + tb + 10);
                v[j].w = fmaf(v[j].w, 1.0f - x10, b_bc);
            } else {
                // v = cols {4,5,6,7}; patch col 4 (RAW_SUM), col 5 (RESULT)
                const float x0  = __ldg(in + tb + 0);
                const float x3  = __ldg(in + tb + 3);
                const float x10 = __ldg(in + tb + 10);
                const float t   = fmaf(x3, 1.0f - x10, b_bc);
                v[j].x = fmaf(x0, t, v[j].x);                 // rawsum

                const unsigned k = (i >> 4) & 7u;             // token index
                if (k >= 3u) {
                    const float* p = in + tb - 3 * 64;        // token k-3
                    const float tp = fmaf(__ldg(p + 3), 1.0f - __ldg(p + 10), b_bc);
                    v[j].y += fmaf(__ldg(p + 0), tp, __ldg(p + 4)); // + rawsum[k-3]
                }
            }
        }
    }

#pragma unroll
    for (int j = 0; j < VEC; j++)
        __stcs(out4 + i0 + j * THREADS, v[j]);
}

extern "C" void kernel_launch(void* const* d_in, const int* in_sizes, int n_in,
                              void* d_out, int out_size)
{
    const float* x = (const float*)d_in[0];
    float* out = (float*)d_out;

    int total = in_sizes[0];                  // BATCH * 8 * 64 floats
    if (total <= 0) total = out_size;
    const int total4 = total / 4;             // float4 count (16,777,216)
    const int blocks = total4 / BLK4;         // 16384
    nibble_stream4b_kernel<<<blocks, THREADS>>>(x, out);
}